// round 5
// baseline (speedup 1.0000x reference)
#include <cuda_runtime.h>
#include <stdint.h>

#define NN    100000
#define INC   256
#define HIDC  64
#define OC    40
#define E1MAX 1600000
#define E2MAX 3200000

static __device__ float g_h0[(size_t)NN * HIDC];
static __device__ float g_g1[(size_t)NN * OC];
static __device__ float g_g2[(size_t)NN * OC];
static __device__ int   g_ptr1[NN + 1];
static __device__ int   g_ptr2[NN + 1];
static __device__ int   g_cur1[NN];
static __device__ int   g_cur2[NN];
static __device__ int2  g_csr1[E1MAX];
static __device__ int2  g_csr2[E2MAX];

// ---------------- packed fp32 helpers (FFMA2 via PTX fma.rn.f32x2) ----------
__device__ __forceinline__ unsigned long long fma2(unsigned long long a,
                                                   unsigned long long b,
                                                   unsigned long long c) {
    unsigned long long d;
    asm("fma.rn.f32x2 %0, %1, %2, %3;" : "=l"(d) : "l"(a), "l"(b), "l"(c));
    return d;
}
__device__ __forceinline__ unsigned long long dup2(float x) {
    unsigned long long d;
    asm("mov.b64 %0, {%1, %1};" : "=l"(d) : "f"(x));
    return d;
}
__device__ __forceinline__ float2 unpk(unsigned long long v) {
    float2 r;
    asm("mov.b64 {%0, %1}, %2;" : "=f"(r.x), "=f"(r.y) : "l"(v));
    return r;
}

// ---------------------------------------------------------------------------
// GEMM1: h0 = x @ fc1_w^T    x[NN,256], w[64,256] -> g_h0[NN,64]
// ---------------------------------------------------------------------------
__global__ __launch_bounds__(256) void gemm1(const float* __restrict__ x,
                                             const float* __restrict__ w) {
    __shared__ __align__(16) float xs[128][36];
    __shared__ __align__(16) float ws_t[32][68];
    const int tid = threadIdx.x;
    const int tx = tid & 15;
    const int ty = tid >> 4;
    const int row0 = blockIdx.x * 128;

    unsigned long long acc0[8], acc1[8];
#pragma unroll
    for (int i = 0; i < 8; i++) { acc0[i] = 0ULL; acc1[i] = 0ULL; }

    for (int k0 = 0; k0 < INC; k0 += 32) {
#pragma unroll
        for (int q = 0; q < 4; q++) {
            int f  = tid + q * 256;
            int k4 = f & 7;
            int r  = f >> 3;
            int gr = min(row0 + r, NN - 1);
            float4 xv = *reinterpret_cast<const float4*>(x + (size_t)gr * INC + k0 + k4 * 4);
            *reinterpret_cast<float4*>(&xs[r][k4 * 4]) = xv;
        }
#pragma unroll
        for (int q = 0; q < 2; q++) {
            int f  = tid + q * 256;
            int k4 = f & 7;
            int n  = f >> 3;
            float4 wv = *reinterpret_cast<const float4*>(w + (size_t)n * INC + k0 + k4 * 4);
            ws_t[k4 * 4 + 0][n] = wv.x;
            ws_t[k4 * 4 + 1][n] = wv.y;
            ws_t[k4 * 4 + 2][n] = wv.z;
            ws_t[k4 * 4 + 3][n] = wv.w;
        }
        __syncthreads();
#pragma unroll 2
        for (int k4 = 0; k4 < 8; k4++) {
            ulonglong2 bb[4];
#pragma unroll
            for (int k = 0; k < 4; k++)
                bb[k] = *reinterpret_cast<const ulonglong2*>(&ws_t[k4 * 4 + k][tx * 4]);
#pragma unroll
            for (int i = 0; i < 8; i++) {
                float4 a4 = *reinterpret_cast<const float4*>(&xs[ty * 8 + i][k4 * 4]);
                unsigned long long aa;
                aa = dup2(a4.x); acc0[i] = fma2(aa, bb[0].x, acc0[i]); acc1[i] = fma2(aa, bb[0].y, acc1[i]);
                aa = dup2(a4.y); acc0[i] = fma2(aa, bb[1].x, acc0[i]); acc1[i] = fma2(aa, bb[1].y, acc1[i]);
                aa = dup2(a4.z); acc0[i] = fma2(aa, bb[2].x, acc0[i]); acc1[i] = fma2(aa, bb[2].y, acc1[i]);
                aa = dup2(a4.w); acc0[i] = fma2(aa, bb[3].x, acc0[i]); acc1[i] = fma2(aa, bb[3].y, acc1[i]);
            }
        }
        __syncthreads();
    }
#pragma unroll
    for (int i = 0; i < 8; i++) {
        int gr = row0 + ty * 8 + i;
        if (gr < NN) {
            float2 lo = unpk(acc0[i]);
            float2 hi = unpk(acc1[i]);
            *reinterpret_cast<float4*>(g_h0 + (size_t)gr * HIDC + tx * 4) =
                make_float4(lo.x, lo.y, hi.x, hi.y);
        }
    }
}

// ---------------------------------------------------------------------------
// PROJ: out[n] = h0[n]@W0^T + b ; g1[n] = h0[n]@W1^T ; g2[n] = h0[n]@W2^T
// ---------------------------------------------------------------------------
__global__ __launch_bounds__(256) void proj(const float* __restrict__ w,
                                            const float* __restrict__ b,
                                            float* __restrict__ out) {
    __shared__ __align__(16) float wt[192][44];
    __shared__ float bs[OC];
    const int tid = threadIdx.x;
    for (int idx = tid; idx < OC * 192; idx += 256) {
        int o = idx / 192;
        int k = idx - o * 192;
        wt[k][o] = w[idx];
    }
    if (tid < OC) bs[tid] = b[tid];
    __syncthreads();

    const int n  = blockIdx.x * 256 + tid;
    const int nn = min(n, NN - 1);
    const float* hrow = g_h0 + (size_t)nn * HIDC;

    float h[HIDC];
#pragma unroll
    for (int k4 = 0; k4 < 16; k4++) {
        float4 h4 = *reinterpret_cast<const float4*>(hrow + k4 * 4);
        h[k4 * 4 + 0] = h4.x; h[k4 * 4 + 1] = h4.y;
        h[k4 * 4 + 2] = h4.z; h[k4 * 4 + 3] = h4.w;
    }

#pragma unroll
    for (int s = 0; s < 3; s++) {
        unsigned long long acc[20];
#pragma unroll
        for (int p = 0; p < 20; p++) acc[p] = 0ULL;
#pragma unroll 4
        for (int k = 0; k < HIDC; k++) {
            unsigned long long hh = dup2(h[k]);
            const float* wrow = &wt[s * 64 + k][0];
#pragma unroll
            for (int p = 0; p < 10; p++) {
                ulonglong2 wv = *reinterpret_cast<const ulonglong2*>(wrow + p * 4);
                acc[p * 2 + 0] = fma2(hh, wv.x, acc[p * 2 + 0]);
                acc[p * 2 + 1] = fma2(hh, wv.y, acc[p * 2 + 1]);
            }
        }
        if (n < NN) {
            float* dst = (s == 0) ? (out + (size_t)n * OC)
                       : (s == 1) ? (g_g1 + (size_t)n * OC)
                                  : (g_g2 + (size_t)n * OC);
#pragma unroll
            for (int p = 0; p < 10; p++) {
                float2 lo = unpk(acc[p * 2 + 0]);
                float2 hi = unpk(acc[p * 2 + 1]);
                float4 v = make_float4(lo.x, lo.y, hi.x, hi.y);
                if (s == 0) {
                    v.x += bs[p * 4 + 0]; v.y += bs[p * 4 + 1];
                    v.z += bs[p * 4 + 2]; v.w += bs[p * 4 + 3];
                }
                *reinterpret_cast<float4*>(dst + p * 4) = v;
            }
        }
    }
}

// ---------------------------------------------------------------------------
// CSR build: zero counts -> histogram -> scan (ptr + cursor) -> scatter
// ---------------------------------------------------------------------------
__global__ void zero_cnt() {
    int i = blockIdx.x * blockDim.x + threadIdx.x;
    if (i < NN)          g_cur1[i] = 0;
    else if (i < 2 * NN) g_cur2[i - NN] = 0;
}

__global__ void hist(const int* __restrict__ r1, int E1,
                     const int* __restrict__ r2, int E2) {
    int i = blockIdx.x * blockDim.x + threadIdx.x;
    if (i < E1)            atomicAdd(&g_cur1[__ldg(r1 + i)], 1);
    else if (i < E1 + E2)  atomicAdd(&g_cur2[__ldg(r2 + i - E1)], 1);
}

// grid=2, block=1024: exclusive scan of counts -> ptr; cursor = start offsets
__global__ __launch_bounds__(1024) void scan2() {
    const int g = blockIdx.x;
    int* cnt = g ? g_cur2 : g_cur1;
    int* ptr = g ? g_ptr2 : g_ptr1;
    const int CH = (NN + 1023) / 1024;   // 98
    const int t  = threadIdx.x;
    const int lo = t * CH;
    const int hi = min(lo + CH, NN);

    int s = 0;
    for (int i = lo; i < hi; i++) s += cnt[i];

    __shared__ int sh[1024];
    sh[t] = s;
    __syncthreads();
    for (int off = 1; off < 1024; off <<= 1) {
        int v = (t >= off) ? sh[t - off] : 0;
        __syncthreads();
        sh[t] += v;
        __syncthreads();
    }
    int run = t ? sh[t - 1] : 0;
    for (int i = lo; i < hi; i++) {
        int c = cnt[i];
        ptr[i] = run;
        cnt[i] = run;       // cursor = start offset
        run += c;
    }
    if (t == 1023) ptr[NN] = sh[1023];
}

__global__ void scatter(const int* __restrict__ r1, const int* __restrict__ c1,
                        const float* __restrict__ v1, int E1,
                        const int* __restrict__ r2, const int* __restrict__ c2,
                        const float* __restrict__ v2, int E2) {
    int i = blockIdx.x * blockDim.x + threadIdx.x;
    if (i < E1) {
        int r = __ldg(r1 + i);
        int pos = atomicAdd(&g_cur1[r], 1);
        g_csr1[pos] = make_int2(__ldg(c1 + i), __float_as_int(__ldg(v1 + i)));
    } else if (i < E1 + E2) {
        int j = i - E1;
        int r = __ldg(r2 + j);
        int pos = atomicAdd(&g_cur2[r], 1);
        g_csr2[pos] = make_int2(__ldg(c2 + j), __float_as_int(__ldg(v2 + j)));
    }
}

// ---------------------------------------------------------------------------
// GATHER: warp per row r:
//   out[r] += sum_{e in csr1[r]} v*g1[c]  +  sum_{e in csr2[r]} v*g2[c]
// Lanes: group = lane/10 (0..2 active), slot = lane%10 (float4 of the 40).
// Each group strides the edge list by 3; cross-group combine via shfl.
// ---------------------------------------------------------------------------
__global__ __launch_bounds__(256) void gather(float* __restrict__ out) {
    const int warp = (int)((blockIdx.x * blockDim.x + threadIdx.x) >> 5);
    if (warp >= NN) return;
    const int r    = warp;
    const int lane = threadIdx.x & 31;
    const int grp  = lane / 10;
    const int slot = lane - grp * 10;
    const bool act = lane < 30;

    float4 acc = make_float4(0.f, 0.f, 0.f, 0.f);

    if (act) {
        int beg = __ldg(&g_ptr1[r]);
        int end = __ldg(&g_ptr1[r + 1]);
        for (int e = beg + grp; e < end; e += 3) {
            int2  ent = __ldg(&g_csr1[e]);
            float v   = __int_as_float(ent.y);
            float4 h  = __ldg(reinterpret_cast<const float4*>(
                              g_g1 + (size_t)ent.x * OC + slot * 4));
            acc.x += v * h.x; acc.y += v * h.y;
            acc.z += v * h.z; acc.w += v * h.w;
        }
        beg = __ldg(&g_ptr2[r]);
        end = __ldg(&g_ptr2[r + 1]);
        for (int e = beg + grp; e < end; e += 3) {
            int2  ent = __ldg(&g_csr2[e]);
            float v   = __int_as_float(ent.y);
            float4 h  = __ldg(reinterpret_cast<const float4*>(
                              g_g2 + (size_t)ent.x * OC + slot * 4));
            acc.x += v * h.x; acc.y += v * h.y;
            acc.z += v * h.z; acc.w += v * h.w;
        }
    }
    // combine the 3 groups: lane s (<10) += lane s+10, lane s+20
    float4 b1, b2;
    b1.x = __shfl_down_sync(0xffffffffu, acc.x, 10);
    b1.y = __shfl_down_sync(0xffffffffu, acc.y, 10);
    b1.z = __shfl_down_sync(0xffffffffu, acc.z, 10);
    b1.w = __shfl_down_sync(0xffffffffu, acc.w, 10);
    b2.x = __shfl_down_sync(0xffffffffu, acc.x, 20);
    b2.y = __shfl_down_sync(0xffffffffu, acc.y, 20);
    b2.z = __shfl_down_sync(0xffffffffu, acc.z, 20);
    b2.w = __shfl_down_sync(0xffffffffu, acc.w, 20);

    if (lane < 10) {
        float* dst = out + (size_t)r * OC + slot * 4;
        float4 o = *reinterpret_cast<const float4*>(dst);   // init from proj
        o.x += acc.x + b1.x + b2.x;
        o.y += acc.y + b1.y + b2.y;
        o.z += acc.z + b1.z + b2.z;
        o.w += acc.w + b1.w + b2.w;
        *reinterpret_cast<float4*>(dst) = o;
    }
}

// ---------------------------------------------------------------------------
// Launch: zero -> hist -> scan -> scatter -> gemm1 -> proj -> gather
// ---------------------------------------------------------------------------
extern "C" void kernel_launch(void* const* d_in, const int* in_sizes, int n_in,
                              void* d_out, int out_size) {
    const float* x   = (const float*)d_in[0];
    const int*   a1r = (const int*)  d_in[2];
    const int*   a1c = (const int*)  d_in[3];
    const float* a1v = (const float*)d_in[4];
    const int*   a2r = (const int*)  d_in[5];
    const int*   a2c = (const int*)  d_in[6];
    const float* a2v = (const float*)d_in[7];
    const float* w1  = (const float*)d_in[8];
    const float* w2  = (const float*)d_in[9];
    const float* b2  = (const float*)d_in[10];
    float* out = (float*)d_out;
    const int E1 = in_sizes[4];
    const int E2 = in_sizes[7];
    const int Et = E1 + E2;

    zero_cnt<<<(2 * NN + 255) / 256, 256>>>();
    hist<<<(Et + 255) / 256, 256>>>(a1r, E1, a2r, E2);
    scan2<<<2, 1024>>>();
    scatter<<<(Et + 255) / 256, 256>>>(a1r, a1c, a1v, E1, a2r, a2c, a2v, E2);

    gemm1<<<(NN + 127) / 128, 256>>>(x, w1);
    proj<<<(NN + 255) / 256, 256>>>(w2, b2, out);

    gather<<<(NN * 32 + 255) / 256, 256>>>(out);
}

// round 7
// speedup vs baseline: 1.5299x; 1.5299x over previous
#include <cuda_runtime.h>
#include <stdint.h>

#define NN     100000
#define INC    256
#define HIDC   64
#define OC     40
#define MAXD1  64
#define MAXD2  80
#define OVFMAX 65536

static __device__ float g_h0[(size_t)NN * HIDC];
static __device__ float g_g1[(size_t)NN * OC];
static __device__ float g_g2[(size_t)NN * OC];
static __device__ int   g_cnt1[NN];
static __device__ int   g_cnt2[NN];
static __device__ int2  g_slot1[(size_t)NN * MAXD1];   // (col, val-bits)
static __device__ int2  g_slot2[(size_t)NN * MAXD2];
static __device__ int   g_ovf_n;
static __device__ int4  g_ovf[OVFMAX];                 // (graph, row, col, val-bits)

// ---------------- packed fp32 helpers (FFMA2 via PTX fma.rn.f32x2) ----------
__device__ __forceinline__ unsigned long long fma2(unsigned long long a,
                                                   unsigned long long b,
                                                   unsigned long long c) {
    unsigned long long d;
    asm("fma.rn.f32x2 %0, %1, %2, %3;" : "=l"(d) : "l"(a), "l"(b), "l"(c));
    return d;
}
__device__ __forceinline__ unsigned long long dup2(float x) {
    unsigned long long d;
    asm("mov.b64 %0, {%1, %1};" : "=l"(d) : "f"(x));
    return d;
}
__device__ __forceinline__ float2 unpk(unsigned long long v) {
    float2 r;
    asm("mov.b64 {%0, %1}, %2;" : "=f"(r.x), "=f"(r.y) : "l"(v));
    return r;
}

// ---------------------------------------------------------------------------
// GEMM1: h0 = x @ fc1_w^T    x[NN,256], w[64,256] -> g_h0[NN,64]
// ---------------------------------------------------------------------------
__global__ __launch_bounds__(256) void gemm1(const float* __restrict__ x,
                                             const float* __restrict__ w) {
    __shared__ __align__(16) float xs[128][36];
    __shared__ __align__(16) float ws_t[32][68];
    const int tid = threadIdx.x;
    const int tx = tid & 15;
    const int ty = tid >> 4;
    const int row0 = blockIdx.x * 128;

    unsigned long long acc0[8], acc1[8];
#pragma unroll
    for (int i = 0; i < 8; i++) { acc0[i] = 0ULL; acc1[i] = 0ULL; }

    for (int k0 = 0; k0 < INC; k0 += 32) {
#pragma unroll
        for (int q = 0; q < 4; q++) {
            int f  = tid + q * 256;
            int k4 = f & 7;
            int r  = f >> 3;
            int gr = min(row0 + r, NN - 1);
            float4 xv = *reinterpret_cast<const float4*>(x + (size_t)gr * INC + k0 + k4 * 4);
            *reinterpret_cast<float4*>(&xs[r][k4 * 4]) = xv;
        }
#pragma unroll
        for (int q = 0; q < 2; q++) {
            int f  = tid + q * 256;
            int k4 = f & 7;
            int n  = f >> 3;
            float4 wv = *reinterpret_cast<const float4*>(w + (size_t)n * INC + k0 + k4 * 4);
            ws_t[k4 * 4 + 0][n] = wv.x;
            ws_t[k4 * 4 + 1][n] = wv.y;
            ws_t[k4 * 4 + 2][n] = wv.z;
            ws_t[k4 * 4 + 3][n] = wv.w;
        }
        __syncthreads();
#pragma unroll 2
        for (int k4 = 0; k4 < 8; k4++) {
            ulonglong2 bb[4];
#pragma unroll
            for (int k = 0; k < 4; k++)
                bb[k] = *reinterpret_cast<const ulonglong2*>(&ws_t[k4 * 4 + k][tx * 4]);
#pragma unroll
            for (int i = 0; i < 8; i++) {
                float4 a4 = *reinterpret_cast<const float4*>(&xs[ty * 8 + i][k4 * 4]);
                unsigned long long aa;
                aa = dup2(a4.x); acc0[i] = fma2(aa, bb[0].x, acc0[i]); acc1[i] = fma2(aa, bb[0].y, acc1[i]);
                aa = dup2(a4.y); acc0[i] = fma2(aa, bb[1].x, acc0[i]); acc1[i] = fma2(aa, bb[1].y, acc1[i]);
                aa = dup2(a4.z); acc0[i] = fma2(aa, bb[2].x, acc0[i]); acc1[i] = fma2(aa, bb[2].y, acc1[i]);
                aa = dup2(a4.w); acc0[i] = fma2(aa, bb[3].x, acc0[i]); acc1[i] = fma2(aa, bb[3].y, acc1[i]);
            }
        }
        __syncthreads();
    }
#pragma unroll
    for (int i = 0; i < 8; i++) {
        int gr = row0 + ty * 8 + i;
        if (gr < NN) {
            float2 lo = unpk(acc0[i]);
            float2 hi = unpk(acc1[i]);
            *reinterpret_cast<float4*>(g_h0 + (size_t)gr * HIDC + tx * 4) =
                make_float4(lo.x, lo.y, hi.x, hi.y);
        }
    }
}

// ---------------------------------------------------------------------------
// PROJ: out[n] = h0[n]@W0^T + b ; g1[n] = h0[n]@W1^T ; g2[n] = h0[n]@W2^T
// ---------------------------------------------------------------------------
__global__ __launch_bounds__(256) void proj(const float* __restrict__ w,
                                            const float* __restrict__ b,
                                            float* __restrict__ out) {
    __shared__ __align__(16) float wt[192][44];
    __shared__ float bs[OC];
    const int tid = threadIdx.x;
    for (int idx = tid; idx < OC * 192; idx += 256) {
        int o = idx / 192;
        int k = idx - o * 192;
        wt[k][o] = w[idx];
    }
    if (tid < OC) bs[tid] = b[tid];
    __syncthreads();

    const int n  = blockIdx.x * 256 + tid;
    const int nn = min(n, NN - 1);
    const float* hrow = g_h0 + (size_t)nn * HIDC;

    float h[HIDC];
#pragma unroll
    for (int k4 = 0; k4 < 16; k4++) {
        float4 h4 = *reinterpret_cast<const float4*>(hrow + k4 * 4);
        h[k4 * 4 + 0] = h4.x; h[k4 * 4 + 1] = h4.y;
        h[k4 * 4 + 2] = h4.z; h[k4 * 4 + 3] = h4.w;
    }

#pragma unroll
    for (int s = 0; s < 3; s++) {
        unsigned long long acc[20];
#pragma unroll
        for (int p = 0; p < 20; p++) acc[p] = 0ULL;
#pragma unroll 4
        for (int k = 0; k < HIDC; k++) {
            unsigned long long hh = dup2(h[k]);
            const float* wrow = &wt[s * 64 + k][0];
#pragma unroll
            for (int p = 0; p < 10; p++) {
                ulonglong2 wv = *reinterpret_cast<const ulonglong2*>(wrow + p * 4);
                acc[p * 2 + 0] = fma2(hh, wv.x, acc[p * 2 + 0]);
                acc[p * 2 + 1] = fma2(hh, wv.y, acc[p * 2 + 1]);
            }
        }
        if (n < NN) {
            float* dst = (s == 0) ? (out + (size_t)n * OC)
                       : (s == 1) ? (g_g1 + (size_t)n * OC)
                                  : (g_g2 + (size_t)n * OC);
#pragma unroll
            for (int p = 0; p < 10; p++) {
                float2 lo = unpk(acc[p * 2 + 0]);
                float2 hi = unpk(acc[p * 2 + 1]);
                float4 v = make_float4(lo.x, lo.y, hi.x, hi.y);
                if (s == 0) {
                    v.x += bs[p * 4 + 0]; v.y += bs[p * 4 + 1];
                    v.z += bs[p * 4 + 2]; v.w += bs[p * 4 + 3];
                }
                *reinterpret_cast<float4*>(dst + p * 4) = v;
            }
        }
    }
}

// ---------------------------------------------------------------------------
// Binning: zero counters -> scatter edges into fixed-stride per-row bins.
// Overflow (vanishingly rare) goes to a side list handled by fixup.
// ---------------------------------------------------------------------------
__global__ void zero_cnt() {
    int i = blockIdx.x * blockDim.x + threadIdx.x;
    if (i < NN)          g_cnt1[i] = 0;
    else if (i < 2 * NN) g_cnt2[i - NN] = 0;
    if (i == 0) g_ovf_n = 0;
}

__global__ void scatter(const int* __restrict__ r1, const int* __restrict__ c1,
                        const float* __restrict__ v1, int E1,
                        const int* __restrict__ r2, const int* __restrict__ c2,
                        const float* __restrict__ v2, int E2) {
    int i = blockIdx.x * blockDim.x + threadIdx.x;
    if (i < E1) {
        int r = __ldg(r1 + i);
        int c = __ldg(c1 + i);
        int v = __float_as_int(__ldg(v1 + i));
        int p = atomicAdd(&g_cnt1[r], 1);
        if (p < MAXD1) {
            g_slot1[(size_t)r * MAXD1 + p] = make_int2(c, v);
        } else {
            int o = atomicAdd(&g_ovf_n, 1);
            if (o < OVFMAX) g_ovf[o] = make_int4(0, r, c, v);
        }
    } else if (i < E1 + E2) {
        int j = i - E1;
        int r = __ldg(r2 + j);
        int c = __ldg(c2 + j);
        int v = __float_as_int(__ldg(v2 + j));
        int p = atomicAdd(&g_cnt2[r], 1);
        if (p < MAXD2) {
            g_slot2[(size_t)r * MAXD2 + p] = make_int2(c, v);
        } else {
            int o = atomicAdd(&g_ovf_n, 1);
            if (o < OVFMAX) g_ovf[o] = make_int4(1, r, c, v);
        }
    }
}

// ---------------------------------------------------------------------------
// GATHER: 2 warps per row (one per graph). Warp: 3 edges x 10 float4-lanes,
// unroll-2. Capture-first 3-way shfl combine, then one 10-lane
// red.global.add.v4 into proj-initialized out.
// ---------------------------------------------------------------------------
__global__ __launch_bounds__(256) void gather(float* __restrict__ out) {
    const int w = (int)((blockIdx.x * blockDim.x + threadIdx.x) >> 5);
    if (w >= 2 * NN) return;
    const int r = w >> 1;
    const int g = w & 1;

    const int2*  slots;
    const float* G;
    int cnt;
    if (g == 0) {
        slots = g_slot1 + (size_t)r * MAXD1;
        G     = g_g1;
        cnt   = min(__ldg(&g_cnt1[r]), MAXD1);
    } else {
        slots = g_slot2 + (size_t)r * MAXD2;
        G     = g_g2;
        cnt   = min(__ldg(&g_cnt2[r]), MAXD2);
    }

    const int lane = threadIdx.x & 31;
    const int grp  = lane / 10;            // 0..2 active, 3 = idle
    const int slot = lane - grp * 10;
    const bool act = lane < 30;

    float4 acc = make_float4(0.f, 0.f, 0.f, 0.f);
    if (act) {
        int e = grp;
        for (; e + 3 < cnt; e += 6) {
            int2 ea = __ldg(slots + e);
            int2 eb = __ldg(slots + e + 3);
            float4 ha = __ldg(reinterpret_cast<const float4*>(
                              G + (size_t)ea.x * OC + slot * 4));
            float4 hb = __ldg(reinterpret_cast<const float4*>(
                              G + (size_t)eb.x * OC + slot * 4));
            float va = __int_as_float(ea.y);
            float vb = __int_as_float(eb.y);
            acc.x += va * ha.x + vb * hb.x;
            acc.y += va * ha.y + vb * hb.y;
            acc.z += va * ha.z + vb * hb.z;
            acc.w += va * ha.w + vb * hb.w;
        }
        if (e < cnt) {
            int2 ea = __ldg(slots + e);
            float4 ha = __ldg(reinterpret_cast<const float4*>(
                              G + (size_t)ea.x * OC + slot * 4));
            float va = __int_as_float(ea.y);
            acc.x += va * ha.x; acc.y += va * ha.y;
            acc.z += va * ha.z; acc.w += va * ha.w;
        }
    }
    // capture-first combine: both shuffles read the ORIGINAL acc
    float4 b1, b2;
    b1.x = __shfl_down_sync(0xffffffffu, acc.x, 10);
    b1.y = __shfl_down_sync(0xffffffffu, acc.y, 10);
    b1.z = __shfl_down_sync(0xffffffffu, acc.z, 10);
    b1.w = __shfl_down_sync(0xffffffffu, acc.w, 10);
    b2.x = __shfl_down_sync(0xffffffffu, acc.x, 20);
    b2.y = __shfl_down_sync(0xffffffffu, acc.y, 20);
    b2.z = __shfl_down_sync(0xffffffffu, acc.z, 20);
    b2.w = __shfl_down_sync(0xffffffffu, acc.w, 20);

    if (lane < 10) {
        float* dst = out + (size_t)r * OC + slot * 4;
        float4 s = make_float4(acc.x + b1.x + b2.x, acc.y + b1.y + b2.y,
                               acc.z + b1.z + b2.z, acc.w + b1.w + b2.w);
        asm volatile("red.global.add.v4.f32 [%0], {%1,%2,%3,%4};"
                     :: "l"(dst), "f"(s.x), "f"(s.y), "f"(s.z), "f"(s.w)
                     : "memory");
    }
}

// ---------------------------------------------------------------------------
// FIXUP: process overflow edges (normally zero of them).
// ---------------------------------------------------------------------------
__global__ void fixup(float* __restrict__ out) {
    int n = g_ovf_n;
    if (n > OVFMAX) n = OVFMAX;
    for (int i = threadIdx.x; i < n; i += blockDim.x) {
        int4 e = g_ovf[i];
        const float* G = e.x ? g_g2 : g_g1;
        float v = __int_as_float(e.w);
        for (int j = 0; j < OC; j++) {
            float p = v * G[(size_t)e.z * OC + j];
            asm volatile("red.global.add.f32 [%0], %1;"
                         :: "l"(out + (size_t)e.y * OC + j), "f"(p) : "memory");
        }
    }
}

// ---------------------------------------------------------------------------
// Launch: zero -> scatter -> gemm1 -> proj -> gather -> fixup
// ---------------------------------------------------------------------------
extern "C" void kernel_launch(void* const* d_in, const int* in_sizes, int n_in,
                              void* d_out, int out_size) {
    const float* x   = (const float*)d_in[0];
    const int*   a1r = (const int*)  d_in[2];
    const int*   a1c = (const int*)  d_in[3];
    const float* a1v = (const float*)d_in[4];
    const int*   a2r = (const int*)  d_in[5];
    const int*   a2c = (const int*)  d_in[6];
    const float* a2v = (const float*)d_in[7];
    const float* w1  = (const float*)d_in[8];
    const float* w2  = (const float*)d_in[9];
    const float* b2  = (const float*)d_in[10];
    float* out = (float*)d_out;
    const int E1 = in_sizes[4];
    const int E2 = in_sizes[7];
    const int Et = E1 + E2;

    zero_cnt<<<(2 * NN + 255) / 256, 256>>>();
    scatter<<<(Et + 255) / 256, 256>>>(a1r, a1c, a1v, E1, a2r, a2c, a2v, E2);

    gemm1<<<(NN + 127) / 128, 256>>>(x, w1);
    proj<<<(NN + 255) / 256, 256>>>(w2, b2, out);

    gather<<<(2 * NN * 32 + 255) / 256, 256>>>(out);
    fixup<<<1, 256>>>(out);
}

// round 8
// speedup vs baseline: 1.5740x; 1.0288x over previous
#include <cuda_runtime.h>
#include <stdint.h>

#define NN     100000
#define INC    256
#define HIDC   64
#define OC     40
#define MAXD1  64
#define MAXD2  80
#define OVFMAX 65536

static __device__ float g_h0[(size_t)NN * HIDC];
static __device__ float g_g1[(size_t)NN * OC];
static __device__ float g_g2[(size_t)NN * OC];
static __device__ int   g_cnt1[NN];
static __device__ int   g_cnt2[NN];
static __device__ int2  g_slot1[(size_t)NN * MAXD1];   // (col, val-bits)
static __device__ int2  g_slot2[(size_t)NN * MAXD2];
static __device__ int   g_ovf_n;
static __device__ int4  g_ovf[OVFMAX];                 // (graph, row, col, val-bits)

// ---------------- packed fp32 helpers (FFMA2 via PTX fma.rn.f32x2) ----------
__device__ __forceinline__ unsigned long long fma2(unsigned long long a,
                                                   unsigned long long b,
                                                   unsigned long long c) {
    unsigned long long d;
    asm("fma.rn.f32x2 %0, %1, %2, %3;" : "=l"(d) : "l"(a), "l"(b), "l"(c));
    return d;
}
__device__ __forceinline__ unsigned long long dup2(float x) {
    unsigned long long d;
    asm("mov.b64 %0, {%1, %1};" : "=l"(d) : "f"(x));
    return d;
}
__device__ __forceinline__ float2 unpk(unsigned long long v) {
    float2 r;
    asm("mov.b64 {%0, %1}, %2;" : "=f"(r.x), "=f"(r.y) : "l"(v));
    return r;
}

// ---------------------------------------------------------------------------
// GEMM1: h0 = x @ fc1_w^T    x[NN,256], w[64,256] -> g_h0[NN,64]
// ---------------------------------------------------------------------------
__global__ __launch_bounds__(256) void gemm1(const float* __restrict__ x,
                                             const float* __restrict__ w) {
    __shared__ __align__(16) float xs[128][36];
    __shared__ __align__(16) float ws_t[32][68];
    const int tid = threadIdx.x;
    const int tx = tid & 15;
    const int ty = tid >> 4;
    const int row0 = blockIdx.x * 128;

    unsigned long long acc0[8], acc1[8];
#pragma unroll
    for (int i = 0; i < 8; i++) { acc0[i] = 0ULL; acc1[i] = 0ULL; }

    for (int k0 = 0; k0 < INC; k0 += 32) {
#pragma unroll
        for (int q = 0; q < 4; q++) {
            int f  = tid + q * 256;
            int k4 = f & 7;
            int r  = f >> 3;
            int gr = min(row0 + r, NN - 1);
            float4 xv = *reinterpret_cast<const float4*>(x + (size_t)gr * INC + k0 + k4 * 4);
            *reinterpret_cast<float4*>(&xs[r][k4 * 4]) = xv;
        }
#pragma unroll
        for (int q = 0; q < 2; q++) {
            int f  = tid + q * 256;
            int k4 = f & 7;
            int n  = f >> 3;
            float4 wv = *reinterpret_cast<const float4*>(w + (size_t)n * INC + k0 + k4 * 4);
            ws_t[k4 * 4 + 0][n] = wv.x;
            ws_t[k4 * 4 + 1][n] = wv.y;
            ws_t[k4 * 4 + 2][n] = wv.z;
            ws_t[k4 * 4 + 3][n] = wv.w;
        }
        __syncthreads();
#pragma unroll 2
        for (int k4 = 0; k4 < 8; k4++) {
            ulonglong2 bb[4];
#pragma unroll
            for (int k = 0; k < 4; k++)
                bb[k] = *reinterpret_cast<const ulonglong2*>(&ws_t[k4 * 4 + k][tx * 4]);
#pragma unroll
            for (int i = 0; i < 8; i++) {
                float4 a4 = *reinterpret_cast<const float4*>(&xs[ty * 8 + i][k4 * 4]);
                unsigned long long aa;
                aa = dup2(a4.x); acc0[i] = fma2(aa, bb[0].x, acc0[i]); acc1[i] = fma2(aa, bb[0].y, acc1[i]);
                aa = dup2(a4.y); acc0[i] = fma2(aa, bb[1].x, acc0[i]); acc1[i] = fma2(aa, bb[1].y, acc1[i]);
                aa = dup2(a4.z); acc0[i] = fma2(aa, bb[2].x, acc0[i]); acc1[i] = fma2(aa, bb[2].y, acc1[i]);
                aa = dup2(a4.w); acc0[i] = fma2(aa, bb[3].x, acc0[i]); acc1[i] = fma2(aa, bb[3].y, acc1[i]);
            }
        }
        __syncthreads();
    }
#pragma unroll
    for (int i = 0; i < 8; i++) {
        int gr = row0 + ty * 8 + i;
        if (gr < NN) {
            float2 lo = unpk(acc0[i]);
            float2 hi = unpk(acc1[i]);
            *reinterpret_cast<float4*>(g_h0 + (size_t)gr * HIDC + tx * 4) =
                make_float4(lo.x, lo.y, hi.x, hi.y);
        }
    }
}

// ---------------------------------------------------------------------------
// PROJ2: register-tiled GEMM. Block = 128 rows x 128 cols (120 real),
// cols [0:40)=out(+bias), [40:80)=g1, [80:120)=g2, [120:128)=zero pad.
// Thread = 8 rows x 8 cols; per k4: 16 LDS.128 -> 128 FFMA2 (ratio 8).
// ---------------------------------------------------------------------------
__global__ __launch_bounds__(256) void proj2(const float* __restrict__ w,
                                             const float* __restrict__ b,
                                             float* __restrict__ out) {
    __shared__ __align__(16) float hs[128][68];    // [row][k]
    __shared__ __align__(16) float wt[64][132];    // [k][col]
    __shared__ float bs[OC];
    const int tid = threadIdx.x;
    const int row0 = blockIdx.x * 128;

    // weights: wt[k][c] = w[(c%40)][ (c/40)*64 + k ], zero pad c>=120
    for (int idx = tid; idx < 64 * 128; idx += 256) {
        int k = idx >> 7;
        int c = idx & 127;
        float val = 0.f;
        if (c < 120) {
            int o = c % 40;
            int s = c / 40;
            val = w[o * 192 + s * 64 + k];
        }
        wt[k][c] = val;
    }
    if (tid < OC) bs[tid] = b[tid];
    // h0 tile: 128 rows x 64 floats, coalesced float4
#pragma unroll
    for (int q = 0; q < 8; q++) {
        int f  = tid + q * 256;
        int k4 = f & 15;
        int r  = f >> 4;
        int gr = min(row0 + r, NN - 1);
        *reinterpret_cast<float4*>(&hs[r][k4 * 4]) =
            *reinterpret_cast<const float4*>(g_h0 + (size_t)gr * HIDC + k4 * 4);
    }
    __syncthreads();

    const int tx = tid & 15;       // col group: cols tx*8 .. tx*8+7
    const int ty = tid >> 4;       // row group: rows ty*8 .. ty*8+7

    unsigned long long acc[8][4];
#pragma unroll
    for (int i = 0; i < 8; i++)
#pragma unroll
        for (int j = 0; j < 4; j++) acc[i][j] = 0ULL;

#pragma unroll 2
    for (int k4 = 0; k4 < 16; k4++) {
        ulonglong2 bb[4][2];
#pragma unroll
        for (int k = 0; k < 4; k++) {
            bb[k][0] = *reinterpret_cast<const ulonglong2*>(&wt[k4 * 4 + k][tx * 8]);
            bb[k][1] = *reinterpret_cast<const ulonglong2*>(&wt[k4 * 4 + k][tx * 8 + 4]);
        }
#pragma unroll
        for (int i = 0; i < 8; i++) {
            float4 a4 = *reinterpret_cast<const float4*>(&hs[ty * 8 + i][k4 * 4]);
            unsigned long long aa;
            aa = dup2(a4.x);
            acc[i][0] = fma2(aa, bb[0][0].x, acc[i][0]);
            acc[i][1] = fma2(aa, bb[0][0].y, acc[i][1]);
            acc[i][2] = fma2(aa, bb[0][1].x, acc[i][2]);
            acc[i][3] = fma2(aa, bb[0][1].y, acc[i][3]);
            aa = dup2(a4.y);
            acc[i][0] = fma2(aa, bb[1][0].x, acc[i][0]);
            acc[i][1] = fma2(aa, bb[1][0].y, acc[i][1]);
            acc[i][2] = fma2(aa, bb[1][1].x, acc[i][2]);
            acc[i][3] = fma2(aa, bb[1][1].y, acc[i][3]);
            aa = dup2(a4.z);
            acc[i][0] = fma2(aa, bb[2][0].x, acc[i][0]);
            acc[i][1] = fma2(aa, bb[2][0].y, acc[i][1]);
            acc[i][2] = fma2(aa, bb[2][1].x, acc[i][2]);
            acc[i][3] = fma2(aa, bb[2][1].y, acc[i][3]);
            aa = dup2(a4.w);
            acc[i][0] = fma2(aa, bb[3][0].x, acc[i][0]);
            acc[i][1] = fma2(aa, bb[3][0].y, acc[i][1]);
            acc[i][2] = fma2(aa, bb[3][1].x, acc[i][2]);
            acc[i][3] = fma2(aa, bb[3][1].y, acc[i][3]);
        }
    }

    if (tx < 15) {                         // tx==15 = zero pad cols
        const int c0 = tx * 8;
        const int s  = c0 / 40;            // 8-col group never straddles a segment
        const int cb = c0 - s * 40;
        float* base = (s == 0) ? out : (s == 1) ? g_g1 : g_g2;
#pragma unroll
        for (int i = 0; i < 8; i++) {
            int gr = row0 + ty * 8 + i;
            if (gr < NN) {
                float2 p0 = unpk(acc[i][0]);
                float2 p1 = unpk(acc[i][1]);
                float2 p2 = unpk(acc[i][2]);
                float2 p3 = unpk(acc[i][3]);
                float4 v0 = make_float4(p0.x, p0.y, p1.x, p1.y);
                float4 v1 = make_float4(p2.x, p2.y, p3.x, p3.y);
                if (s == 0) {
                    v0.x += bs[cb + 0]; v0.y += bs[cb + 1];
                    v0.z += bs[cb + 2]; v0.w += bs[cb + 3];
                    v1.x += bs[cb + 4]; v1.y += bs[cb + 5];
                    v1.z += bs[cb + 6]; v1.w += bs[cb + 7];
                }
                *reinterpret_cast<float4*>(base + (size_t)gr * OC + cb)     = v0;
                *reinterpret_cast<float4*>(base + (size_t)gr * OC + cb + 4) = v1;
            }
        }
    }
}

// ---------------------------------------------------------------------------
// Binning: zero counters -> scatter edges into fixed-stride per-row bins.
// ---------------------------------------------------------------------------
__global__ void zero_cnt() {
    int i = blockIdx.x * blockDim.x + threadIdx.x;
    if (i < NN)          g_cnt1[i] = 0;
    else if (i < 2 * NN) g_cnt2[i - NN] = 0;
    if (i == 0) g_ovf_n = 0;
}

__global__ void scatter(const int* __restrict__ r1, const int* __restrict__ c1,
                        const float* __restrict__ v1, int E1,
                        const int* __restrict__ r2, const int* __restrict__ c2,
                        const float* __restrict__ v2, int E2) {
    int i = blockIdx.x * blockDim.x + threadIdx.x;
    if (i < E1) {
        int r = __ldg(r1 + i);
        int c = __ldg(c1 + i);
        int v = __float_as_int(__ldg(v1 + i));
        int p = atomicAdd(&g_cnt1[r], 1);
        if (p < MAXD1) {
            g_slot1[(size_t)r * MAXD1 + p] = make_int2(c, v);
        } else {
            int o = atomicAdd(&g_ovf_n, 1);
            if (o < OVFMAX) g_ovf[o] = make_int4(0, r, c, v);
        }
    } else if (i < E1 + E2) {
        int j = i - E1;
        int r = __ldg(r2 + j);
        int c = __ldg(c2 + j);
        int v = __float_as_int(__ldg(v2 + j));
        int p = atomicAdd(&g_cnt2[r], 1);
        if (p < MAXD2) {
            g_slot2[(size_t)r * MAXD2 + p] = make_int2(c, v);
        } else {
            int o = atomicAdd(&g_ovf_n, 1);
            if (o < OVFMAX) g_ovf[o] = make_int4(1, r, c, v);
        }
    }
}

// ---------------------------------------------------------------------------
// GATHER: 2 warps per row (one per graph). Warp: 3 edges x 10 float4-lanes,
// unroll-2. Capture-first 3-way shfl combine, then one 10-lane
// red.global.add.v4 into proj-initialized out.
// ---------------------------------------------------------------------------
__global__ __launch_bounds__(256) void gather(float* __restrict__ out) {
    const int w = (int)((blockIdx.x * blockDim.x + threadIdx.x) >> 5);
    if (w >= 2 * NN) return;
    const int r = w >> 1;
    const int g = w & 1;

    const int2*  slots;
    const float* G;
    int cnt;
    if (g == 0) {
        slots = g_slot1 + (size_t)r * MAXD1;
        G     = g_g1;
        cnt   = min(__ldg(&g_cnt1[r]), MAXD1);
    } else {
        slots = g_slot2 + (size_t)r * MAXD2;
        G     = g_g2;
        cnt   = min(__ldg(&g_cnt2[r]), MAXD2);
    }

    const int lane = threadIdx.x & 31;
    const int grp  = lane / 10;
    const int slot = lane - grp * 10;
    const bool act = lane < 30;

    float4 acc = make_float4(0.f, 0.f, 0.f, 0.f);
    if (act) {
        int e = grp;
        for (; e + 3 < cnt; e += 6) {
            int2 ea = __ldg(slots + e);
            int2 eb = __ldg(slots + e + 3);
            float4 ha = __ldg(reinterpret_cast<const float4*>(
                              G + (size_t)ea.x * OC + slot * 4));
            float4 hb = __ldg(reinterpret_cast<const float4*>(
                              G + (size_t)eb.x * OC + slot * 4));
            float va = __int_as_float(ea.y);
            float vb = __int_as_float(eb.y);
            acc.x += va * ha.x + vb * hb.x;
            acc.y += va * ha.y + vb * hb.y;
            acc.z += va * ha.z + vb * hb.z;
            acc.w += va * ha.w + vb * hb.w;
        }
        if (e < cnt) {
            int2 ea = __ldg(slots + e);
            float4 ha = __ldg(reinterpret_cast<const float4*>(
                              G + (size_t)ea.x * OC + slot * 4));
            float va = __int_as_float(ea.y);
            acc.x += va * ha.x; acc.y += va * ha.y;
            acc.z += va * ha.z; acc.w += va * ha.w;
        }
    }
    // capture-first combine: both shuffles read the ORIGINAL acc
    float4 b1, b2;
    b1.x = __shfl_down_sync(0xffffffffu, acc.x, 10);
    b1.y = __shfl_down_sync(0xffffffffu, acc.y, 10);
    b1.z = __shfl_down_sync(0xffffffffu, acc.z, 10);
    b1.w = __shfl_down_sync(0xffffffffu, acc.w, 10);
    b2.x = __shfl_down_sync(0xffffffffu, acc.x, 20);
    b2.y = __shfl_down_sync(0xffffffffu, acc.y, 20);
    b2.z = __shfl_down_sync(0xffffffffu, acc.z, 20);
    b2.w = __shfl_down_sync(0xffffffffu, acc.w, 20);

    if (lane < 10) {
        float* dst = out + (size_t)r * OC + slot * 4;
        float4 s = make_float4(acc.x + b1.x + b2.x, acc.y + b1.y + b2.y,
                               acc.z + b1.z + b2.z, acc.w + b1.w + b2.w);
        asm volatile("red.global.add.v4.f32 [%0], {%1,%2,%3,%4};"
                     :: "l"(dst), "f"(s.x), "f"(s.y), "f"(s.z), "f"(s.w)
                     : "memory");
    }
}

// ---------------------------------------------------------------------------
// FIXUP: process overflow edges (normally zero of them).
// ---------------------------------------------------------------------------
__global__ void fixup(float* __restrict__ out) {
    int n = g_ovf_n;
    if (n > OVFMAX) n = OVFMAX;
    for (int i = threadIdx.x; i < n; i += blockDim.x) {
        int4 e = g_ovf[i];
        const float* G = e.x ? g_g2 : g_g1;
        float v = __int_as_float(e.w);
        for (int j = 0; j < OC; j++) {
            float p = v * G[(size_t)e.z * OC + j];
            asm volatile("red.global.add.f32 [%0], %1;"
                         :: "l"(out + (size_t)e.y * OC + j), "f"(p) : "memory");
        }
    }
}

// ---------------------------------------------------------------------------
// Launch with capture fork: [zero+scatter] on side stream concurrent with
// [gemm1+proj2]; join before gather.
// ---------------------------------------------------------------------------
extern "C" void kernel_launch(void* const* d_in, const int* in_sizes, int n_in,
                              void* d_out, int out_size) {
    const float* x   = (const float*)d_in[0];
    const int*   a1r = (const int*)  d_in[2];
    const int*   a1c = (const int*)  d_in[3];
    const float* a1v = (const float*)d_in[4];
    const int*   a2r = (const int*)  d_in[5];
    const int*   a2c = (const int*)  d_in[6];
    const float* a2v = (const float*)d_in[7];
    const float* w1  = (const float*)d_in[8];
    const float* w2  = (const float*)d_in[9];
    const float* b2  = (const float*)d_in[10];
    float* out = (float*)d_out;
    const int E1 = in_sizes[4];
    const int E2 = in_sizes[7];
    const int Et = E1 + E2;

    cudaStream_t s2;
    cudaEvent_t  e0, e1;
    cudaStreamCreateWithFlags(&s2, cudaStreamNonBlocking);
    cudaEventCreateWithFlags(&e0, cudaEventDisableTiming);
    cudaEventCreateWithFlags(&e1, cudaEventDisableTiming);

    // fork: side stream does the edge binning
    cudaEventRecord(e0, 0);
    cudaStreamWaitEvent(s2, e0, 0);
    zero_cnt<<<(2 * NN + 255) / 256, 256, 0, s2>>>();
    scatter<<<(Et + 255) / 256, 256, 0, s2>>>(a1r, a1c, a1v, E1,
                                              a2r, a2c, a2v, E2);
    cudaEventRecord(e1, s2);

    // main stream: dense compute
    gemm1<<<(NN + 127) / 128, 256>>>(x, w1);
    proj2<<<(NN + 127) / 128, 256>>>(w2, b2, out);

    // join, then gather
    cudaStreamWaitEvent(0, e1, 0);
    gather<<<(2 * NN * 32 + 255) / 256, 256>>>(out);
    fixup<<<1, 256>>>(out);
}